// round 2
// baseline (speedup 1.0000x reference)
#include <cuda_runtime.h>
#include <math.h>

#define N_NODES 50000
#define N_EDGES 800000
#define TOT_E   (N_EDGES + N_NODES)
#define IN_CH   128
#define HEADS   4
#define OUT_CH  64
#define HC      256
#define NEG_SLOPE 0.2f

// Scratch (device globals: no allocation allowed in kernel_launch)
__device__ float    g_xl[N_NODES * HC];        // projected features [N,256]  (51.2MB, L2-resident)
__device__ float    g_asrc[N_NODES * HEADS];   // per-node src logits
__device__ float    g_adst[N_NODES * HEADS];   // per-node dst logits
__device__ unsigned g_amax[N_NODES * HEADS];   // segment max, order-encoded float
__device__ float    g_den [N_NODES * HEADS];   // segment softmax denominator

// order-preserving float<->uint encoding for atomicMax on floats
__device__ __forceinline__ unsigned fenc(float f) {
    unsigned u = __float_as_uint(f);
    return (u & 0x80000000u) ? ~u : (u | 0x80000000u);
}
__device__ __forceinline__ float fdec(unsigned u) {
    u = (u & 0x80000000u) ? (u ^ 0x80000000u) : ~u;
    return __uint_as_float(u);
}
__device__ __forceinline__ float lrelu(float a) {
    return a > 0.f ? a : NEG_SLOPE * a;
}

// ---------------- K0: zero accumulators + output ----------------
__global__ void k_init(float* __restrict__ out) {
    int i = blockIdx.x * blockDim.x + threadIdx.x;
    const int n4 = N_NODES * HC / 4;          // 3.2M float4
    if (i < n4) ((float4*)out)[i] = make_float4(0.f, 0.f, 0.f, 0.f);
    if (i < N_NODES * HEADS / 4) {
        ((uint4*)g_amax)[i] = make_uint4(0u, 0u, 0u, 0u);   // enc-min sentinel
        ((float4*)g_den)[i] = make_float4(0.f, 0.f, 0.f, 0.f);
    }
}

// ---------------- K1: xl = x @ W^T  (16 nodes per 256-thread block) ------
__global__ void __launch_bounds__(256) k_gemm(const float* __restrict__ x,
                                              const float* __restrict__ W) {
    __shared__ float xs[16 * IN_CH];
    const int n0 = blockIdx.x * 16;           // 50000 = 3125 * 16 exactly
    const int t  = threadIdx.x;               // output channel 0..255

    const float* xsrc = x + (size_t)n0 * IN_CH;
    #pragma unroll
    for (int i = t; i < 16 * IN_CH; i += 256) xs[i] = xsrc[i];
    __syncthreads();

    float acc[16];
    #pragma unroll
    for (int n = 0; n < 16; n++) acc[n] = 0.f;

    const float4* Wr = (const float4*)(W + (size_t)t * IN_CH);
    #pragma unroll
    for (int kt = 0; kt < IN_CH; kt += 16) {
        float4 w0 = Wr[kt / 4 + 0];
        float4 w1 = Wr[kt / 4 + 1];
        float4 w2 = Wr[kt / 4 + 2];
        float4 w3 = Wr[kt / 4 + 3];
        #pragma unroll
        for (int n = 0; n < 16; n++) {
            const float* xr = xs + n * IN_CH + kt;   // broadcast LDS
            float a = acc[n];
            a += w0.x * xr[0]  + w0.y * xr[1]  + w0.z * xr[2]  + w0.w * xr[3];
            a += w1.x * xr[4]  + w1.y * xr[5]  + w1.z * xr[6]  + w1.w * xr[7];
            a += w2.x * xr[8]  + w2.y * xr[9]  + w2.z * xr[10] + w2.w * xr[11];
            a += w3.x * xr[12] + w3.y * xr[13] + w3.z * xr[14] + w3.w * xr[15];
            acc[n] = a;
        }
    }
    #pragma unroll
    for (int n = 0; n < 16; n++)
        g_xl[(size_t)(n0 + n) * HC + t] = acc[n];
}

// ---------------- K1b: per-node attention logits (warp per node-head) ----
__global__ void k_logits(const float* __restrict__ att_src,
                         const float* __restrict__ att_dst) {
    int w    = (blockIdx.x * blockDim.x + threadIdx.x) >> 5;
    int lane = threadIdx.x & 31;
    if (w >= N_NODES * HEADS) return;
    int node = w >> 2, h = w & 3;
    float2 xv = *(const float2*)&g_xl[(size_t)node * HC + h * OUT_CH + lane * 2];
    float2 as = *(const float2*)&att_src[h * OUT_CH + lane * 2];
    float2 ad = *(const float2*)&att_dst[h * OUT_CH + lane * 2];
    float ps = xv.x * as.x + xv.y * as.y;
    float pd = xv.x * ad.x + xv.y * ad.y;
    #pragma unroll
    for (int o = 16; o; o >>= 1) {
        ps += __shfl_xor_sync(0xFFFFFFFFu, ps, o);
        pd += __shfl_xor_sync(0xFFFFFFFFu, pd, o);
    }
    if (lane == 0) { g_asrc[w] = ps; g_adst[w] = pd; }
}

// ---------------- K2: segment max over dst ----------------
__global__ void k_max(const int* __restrict__ ei) {
    int e = blockIdx.x * blockDim.x + threadIdx.x;
    if (e >= TOT_E) return;
    int s, d;
    if (e < N_EDGES) { s = ei[e]; d = ei[N_EDGES + e]; }
    else             { s = d = e - N_EDGES; }
    float4 as = *(const float4*)&g_asrc[(size_t)s * 4];
    float4 ad = *(const float4*)&g_adst[(size_t)d * 4];
    unsigned* mp = &g_amax[(size_t)d * 4];
    atomicMax(mp + 0, fenc(lrelu(as.x + ad.x)));
    atomicMax(mp + 1, fenc(lrelu(as.y + ad.y)));
    atomicMax(mp + 2, fenc(lrelu(as.z + ad.z)));
    atomicMax(mp + 3, fenc(lrelu(as.w + ad.w)));
}

// ---------------- K3: segment sum of exp ----------------
__global__ void k_sum(const int* __restrict__ ei) {
    int e = blockIdx.x * blockDim.x + threadIdx.x;
    if (e >= TOT_E) return;
    int s, d;
    if (e < N_EDGES) { s = ei[e]; d = ei[N_EDGES + e]; }
    else             { s = d = e - N_EDGES; }
    float4 as = *(const float4*)&g_asrc[(size_t)s * 4];
    float4 ad = *(const float4*)&g_adst[(size_t)d * 4];
    uint4  mx = *(const uint4*)&g_amax[(size_t)d * 4];
    float* dp = &g_den[(size_t)d * 4];
    atomicAdd(dp + 0, expf(lrelu(as.x + ad.x) - fdec(mx.x)));
    atomicAdd(dp + 1, expf(lrelu(as.y + ad.y) - fdec(mx.y)));
    atomicAdd(dp + 2, expf(lrelu(as.z + ad.z) - fdec(mx.z)));
    atomicAdd(dp + 3, expf(lrelu(as.w + ad.w) - fdec(mx.w)));
}

// ---------------- K4: weighted scatter-aggregate (warp per edge) --------
__device__ __forceinline__ void red4(float4* p, float a, float b, float c, float d) {
    asm volatile("red.global.add.v4.f32 [%0], {%1, %2, %3, %4};"
                 :: "l"(p), "f"(a), "f"(b), "f"(c), "f"(d) : "memory");
}

__global__ void __launch_bounds__(256) k_agg(const int* __restrict__ ei,
                                             float* __restrict__ out) {
    long long gt = (long long)blockIdx.x * blockDim.x + threadIdx.x;
    int e    = (int)(gt >> 5);
    int lane = (int)(gt & 31);
    if (e >= TOT_E) return;
    int s, d;
    if (e < N_EDGES) { s = ei[e]; d = ei[N_EDGES + e]; }
    else             { s = d = e - N_EDGES; }

    float4 as = *(const float4*)&g_asrc[(size_t)s * 4];   // broadcast loads across warp
    float4 ad = *(const float4*)&g_adst[(size_t)d * 4];
    uint4  mx = *(const uint4*)&g_amax[(size_t)d * 4];
    float4 dn = *(const float4*)&g_den[(size_t)d * 4];

    float coef[4];
    coef[0] = expf(lrelu(as.x + ad.x) - fdec(mx.x)) / dn.x;
    coef[1] = expf(lrelu(as.y + ad.y) - fdec(mx.y)) / dn.y;
    coef[2] = expf(lrelu(as.z + ad.z) - fdec(mx.z)) / dn.z;
    coef[3] = expf(lrelu(as.w + ad.w) - fdec(mx.w)) / dn.w;

    const float4* xs = (const float4*)&g_xl[(size_t)s * HC];
    float4*       op = (float4*)(out + (size_t)d * HC);
    #pragma unroll
    for (int i = 0; i < 2; i++) {
        int idx = lane + i * 32;         // float4 index 0..63; head = idx/16
        float c = coef[idx >> 4];
        float4 v = xs[idx];
        red4(op + idx, v.x * c, v.y * c, v.z * c, v.w * c);
    }
}

// ---------------- K5: bias + ELU epilogue ----------------
__global__ void k_epi(float* __restrict__ out, const float* __restrict__ bias) {
    int i = blockIdx.x * blockDim.x + threadIdx.x;
    if (i >= N_NODES * HC) return;
    float v = out[i] + bias[i & (HC - 1)];
    out[i] = v > 0.f ? v : expm1f(v);
}

extern "C" void kernel_launch(void* const* d_in, const int* in_sizes, int n_in,
                              void* d_out, int out_size) {
    const float* x    = (const float*)d_in[0];
    const int*   ei   = (const int*)d_in[1];    // int32! (JAX x64 disabled)
    const float* W    = (const float*)d_in[2];
    const float* asrc = (const float*)d_in[3];
    const float* adst = (const float*)d_in[4];
    const float* bias = (const float*)d_in[5];
    float* out = (float*)d_out;

    (void)in_sizes; (void)n_in; (void)out_size;

    // K0: zero out + amax + denom
    k_init<<<(N_NODES * HC / 4 + 255) / 256, 256>>>(out);
    // K1: projection GEMM (3125 blocks x 16 nodes)
    k_gemm<<<N_NODES / 16, 256>>>(x, W);
    // K1b: logits, warp per (node, head)
    k_logits<<<(N_NODES * HEADS * 32 + 255) / 256, 256>>>(asrc, adst);
    // K2: segment max
    k_max<<<(TOT_E + 255) / 256, 256>>>(ei);
    // K3: segment exp-sum
    k_sum<<<(TOT_E + 255) / 256, 256>>>(ei);
    // K4: scatter aggregate, warp per edge
    {
        long long threads = (long long)TOT_E * 32;
        k_agg<<<(unsigned)((threads + 255) / 256), 256>>>(ei, out);
    }
    // K5: bias + ELU
    k_epi<<<(N_NODES * HC + 255) / 256, 256>>>(out, bias);
}

// round 3
// speedup vs baseline: 1.4117x; 1.4117x over previous
#include <cuda_runtime.h>
#include <math.h>

#define N_NODES 50000
#define N_EDGES 800000
#define TOT_E   (N_EDGES + N_NODES)
#define IN_CH   128
#define HEADS   4
#define OUT_CH  64
#define HC      256
#define NEG_SLOPE 0.2f
#define SCAN_BLOCKS ((N_NODES + 1023) / 1024)   // 49

// ---- scratch (device globals; no allocation allowed) ----
__device__ float g_xl[N_NODES * HC];        // projected features [N,256] (51.2MB)
__device__ float g_asrc[N_NODES * HEADS];
__device__ float g_adst[N_NODES * HEADS];
__device__ float g_den [N_NODES * HEADS];   // softmax denominators
__device__ float g_exp [TOT_E * HEADS];     // per-edge exp(alpha) cache (13.6MB)
__device__ int   g_deg [N_NODES];           // dst degree histogram
__device__ int   g_incl[N_NODES];           // scan partials
__device__ int   g_bsum[SCAN_BLOCKS];
__device__ int   g_boff[SCAN_BLOCKS];
__device__ int   g_ptr [N_NODES + 1];       // CSR row pointers (by dst)
__device__ int   g_cur [N_NODES];           // fill cursors
__device__ int   g_eid [TOT_E];             // dst-sorted edge ids

__device__ __forceinline__ float lrelu(float a) { return a > 0.f ? a : NEG_SLOPE * a; }

__device__ __forceinline__ void red4(float* p, float a, float b, float c, float d) {
    asm volatile("red.global.add.v4.f32 [%0], {%1, %2, %3, %4};"
                 :: "l"(p), "f"(a), "f"(b), "f"(c), "f"(d) : "memory");
}

// decode edge e -> (src, dst); e >= N_EDGES are self loops
__device__ __forceinline__ void edge_sd(const int* __restrict__ ei, int e, int& s, int& d) {
    if (e < N_EDGES) { s = ei[e]; d = ei[N_EDGES + e]; }
    else             { s = d = e - N_EDGES; }
}

// ---------------- K0: zero den + deg ----------------
__global__ void k_init() {
    int i = blockIdx.x * blockDim.x + threadIdx.x;
    if (i < N_NODES) {
        g_deg[i] = 0;
        ((float4*)g_den)[i] = make_float4(0.f, 0.f, 0.f, 0.f);
    }
}

// ---------------- K1: xl = x @ W^T (16 nodes / 256-thread block) ---------
__global__ void __launch_bounds__(256) k_gemm(const float* __restrict__ x,
                                              const float* __restrict__ W) {
    __shared__ float xs[16 * IN_CH];
    const int n0 = blockIdx.x * 16;       // 50000 = 3125 * 16
    const int t  = threadIdx.x;

    const float* xsrc = x + (size_t)n0 * IN_CH;
    #pragma unroll
    for (int i = t; i < 16 * IN_CH; i += 256) xs[i] = xsrc[i];
    __syncthreads();

    float acc[16];
    #pragma unroll
    for (int n = 0; n < 16; n++) acc[n] = 0.f;

    const float4* Wr = (const float4*)(W + (size_t)t * IN_CH);
    #pragma unroll
    for (int kt = 0; kt < IN_CH; kt += 16) {
        float4 w0 = Wr[kt / 4 + 0];
        float4 w1 = Wr[kt / 4 + 1];
        float4 w2 = Wr[kt / 4 + 2];
        float4 w3 = Wr[kt / 4 + 3];
        #pragma unroll
        for (int n = 0; n < 16; n++) {
            const float* xr = xs + n * IN_CH + kt;
            float a = acc[n];
            a += w0.x * xr[0]  + w0.y * xr[1]  + w0.z * xr[2]  + w0.w * xr[3];
            a += w1.x * xr[4]  + w1.y * xr[5]  + w1.z * xr[6]  + w1.w * xr[7];
            a += w2.x * xr[8]  + w2.y * xr[9]  + w2.z * xr[10] + w2.w * xr[11];
            a += w3.x * xr[12] + w3.y * xr[13] + w3.z * xr[14] + w3.w * xr[15];
            acc[n] = a;
        }
    }
    #pragma unroll
    for (int n = 0; n < 16; n++)
        g_xl[(size_t)(n0 + n) * HC + t] = acc[n];
}

// ---------------- K2: per-node attention logits ----------------
__global__ void k_logits(const float* __restrict__ att_src,
                         const float* __restrict__ att_dst) {
    int w    = (blockIdx.x * blockDim.x + threadIdx.x) >> 5;
    int lane = threadIdx.x & 31;
    if (w >= N_NODES * HEADS) return;
    int node = w >> 2, h = w & 3;
    float2 xv = *(const float2*)&g_xl[(size_t)node * HC + h * OUT_CH + lane * 2];
    float2 as = *(const float2*)&att_src[h * OUT_CH + lane * 2];
    float2 ad = *(const float2*)&att_dst[h * OUT_CH + lane * 2];
    float ps = xv.x * as.x + xv.y * as.y;
    float pd = xv.x * ad.x + xv.y * ad.y;
    #pragma unroll
    for (int o = 16; o; o >>= 1) {
        ps += __shfl_xor_sync(0xFFFFFFFFu, ps, o);
        pd += __shfl_xor_sync(0xFFFFFFFFu, pd, o);
    }
    if (lane == 0) { g_asrc[w] = ps; g_adst[w] = pd; }
}

// ---------------- K3: dst-degree histogram ----------------
__global__ void k_hist(const int* __restrict__ ei) {
    int e = blockIdx.x * blockDim.x + threadIdx.x;
    if (e >= TOT_E) return;
    int d = (e < N_EDGES) ? ei[N_EDGES + e] : (e - N_EDGES);
    atomicAdd(&g_deg[d], 1);
}

// ---------------- K4a/b/c: prefix scan of degrees -> CSR ptr -----------
__global__ void __launch_bounds__(1024) k_scanA() {
    __shared__ int s[1024];
    int i = blockIdx.x * 1024 + threadIdx.x;
    int v = (i < N_NODES) ? g_deg[i] : 0;
    s[threadIdx.x] = v;
    __syncthreads();
    #pragma unroll
    for (int off = 1; off < 1024; off <<= 1) {
        int t = (threadIdx.x >= off) ? s[threadIdx.x - off] : 0;
        __syncthreads();
        s[threadIdx.x] += t;
        __syncthreads();
    }
    if (i < N_NODES) g_incl[i] = s[threadIdx.x];
    if (threadIdx.x == 1023) g_bsum[blockIdx.x] = s[1023];
}
__global__ void k_scanB() {
    if (threadIdx.x == 0) {
        int run = 0;
        for (int b = 0; b < SCAN_BLOCKS; b++) { g_boff[b] = run; run += g_bsum[b]; }
    }
}
__global__ void __launch_bounds__(1024) k_scanC() {
    int i = blockIdx.x * 1024 + threadIdx.x;
    if (i >= N_NODES) return;
    int incl = g_incl[i] + g_boff[blockIdx.x];
    int excl = incl - g_deg[i];
    g_ptr[i] = excl;
    g_cur[i] = excl;
    if (i == N_NODES - 1) g_ptr[N_NODES] = incl;
}

// ---------------- K5: fill dst-sorted edge ids ----------------
__global__ void k_fill(const int* __restrict__ ei) {
    int e = blockIdx.x * blockDim.x + threadIdx.x;
    if (e >= TOT_E) return;
    int d = (e < N_EDGES) ? ei[N_EDGES + e] : (e - N_EDGES);
    int pos = atomicAdd(&g_cur[d], 1);
    g_eid[pos] = e;
}

// ---------------- K6: exp(alpha) per edge + denominators ----------------
__global__ void k_sum(const int* __restrict__ ei) {
    int e = blockIdx.x * blockDim.x + threadIdx.x;
    if (e >= TOT_E) return;
    int s, d;
    edge_sd(ei, e, s, d);
    float4 as = *(const float4*)&g_asrc[(size_t)s * 4];
    float4 ad = *(const float4*)&g_adst[(size_t)d * 4];
    float4 ex;
    ex.x = expf(lrelu(as.x + ad.x));
    ex.y = expf(lrelu(as.y + ad.y));
    ex.z = expf(lrelu(as.z + ad.z));
    ex.w = expf(lrelu(as.w + ad.w));
    *(float4*)&g_exp[(size_t)e * 4] = ex;
    red4(&g_den[(size_t)d * 4], ex.x, ex.y, ex.z, ex.w);
}

// ---------------- K7: gather-aggregate, warp per node, fused epilogue ---
__global__ void __launch_bounds__(256) k_agg(const int* __restrict__ ei,
                                             const float* __restrict__ bias,
                                             float* __restrict__ out) {
    int w    = (blockIdx.x * blockDim.x + threadIdx.x) >> 5;   // node id
    int lane = threadIdx.x & 31;
    if (w >= N_NODES) return;
    const int d  = w;
    const int p0 = g_ptr[d];
    const int p1 = g_ptr[d + 1];

    float4 den = *(const float4*)&g_den[(size_t)d * 4];
    float4 idn = make_float4(1.f / den.x, 1.f / den.y, 1.f / den.z, 1.f / den.w);
    // lane covers float4 indices {lane, lane+32} -> heads {lane>>4, 2+(lane>>4)}
    const bool lo = (lane < 16);

    float4 a0 = make_float4(0.f, 0.f, 0.f, 0.f);
    float4 a1 = make_float4(0.f, 0.f, 0.f, 0.f);

    for (int p = p0; p < p1; p++) {
        int eid = g_eid[p];                               // broadcast
        int s   = (eid < N_EDGES) ? ei[eid] : d;          // broadcast
        float4 ex = *(const float4*)&g_exp[(size_t)eid * 4];
        float c0 = lo ? ex.x * idn.x : ex.y * idn.y;
        float c1 = lo ? ex.z * idn.z : ex.w * idn.w;
        const float4* xs = (const float4*)&g_xl[(size_t)s * HC];
        float4 v0 = xs[lane];
        float4 v1 = xs[lane + 32];
        a0.x += c0 * v0.x; a0.y += c0 * v0.y; a0.z += c0 * v0.z; a0.w += c0 * v0.w;
        a1.x += c1 * v1.x; a1.y += c1 * v1.y; a1.z += c1 * v1.z; a1.w += c1 * v1.w;
    }

    float4 b0 = ((const float4*)bias)[lane];
    float4 b1 = ((const float4*)bias)[lane + 32];
    a0.x += b0.x; a0.y += b0.y; a0.z += b0.z; a0.w += b0.w;
    a1.x += b1.x; a1.y += b1.y; a1.z += b1.z; a1.w += b1.w;
    // ELU
    a0.x = a0.x > 0.f ? a0.x : expm1f(a0.x);
    a0.y = a0.y > 0.f ? a0.y : expm1f(a0.y);
    a0.z = a0.z > 0.f ? a0.z : expm1f(a0.z);
    a0.w = a0.w > 0.f ? a0.w : expm1f(a0.w);
    a1.x = a1.x > 0.f ? a1.x : expm1f(a1.x);
    a1.y = a1.y > 0.f ? a1.y : expm1f(a1.y);
    a1.z = a1.z > 0.f ? a1.z : expm1f(a1.z);
    a1.w = a1.w > 0.f ? a1.w : expm1f(a1.w);

    float4* op = (float4*)(out + (size_t)d * HC);
    op[lane]      = a0;
    op[lane + 32] = a1;
}

extern "C" void kernel_launch(void* const* d_in, const int* in_sizes, int n_in,
                              void* d_out, int out_size) {
    const float* x    = (const float*)d_in[0];
    const int*   ei   = (const int*)d_in[1];    // int32 (JAX x64 disabled)
    const float* W    = (const float*)d_in[2];
    const float* asrc = (const float*)d_in[3];
    const float* adst = (const float*)d_in[4];
    const float* bias = (const float*)d_in[5];
    float* out = (float*)d_out;

    (void)in_sizes; (void)n_in; (void)out_size;

    k_init<<<(N_NODES + 255) / 256, 256>>>();
    k_gemm<<<N_NODES / 16, 256>>>(x, W);
    k_logits<<<(N_NODES * HEADS * 32 + 255) / 256, 256>>>(asrc, adst);
    k_hist<<<(TOT_E + 255) / 256, 256>>>(ei);
    k_scanA<<<SCAN_BLOCKS, 1024>>>();
    k_scanB<<<1, 32>>>();
    k_scanC<<<SCAN_BLOCKS, 1024>>>();
    k_fill<<<(TOT_E + 255) / 256, 256>>>(ei);
    k_sum<<<(TOT_E + 255) / 256, 256>>>(ei);
    k_agg<<<(N_NODES * 32 + 255) / 256, 256>>>(ei, bias, out);
}

// round 4
// speedup vs baseline: 1.6067x; 1.1381x over previous
#include <cuda_runtime.h>
#include <math.h>

#define N_NODES 50000
#define N_EDGES 800000
#define TOT_E   (N_EDGES + N_NODES)
#define IN_CH   128
#define HEADS   4
#define OUT_CH  64
#define HC      256
#define NEG_SLOPE 0.2f
#define SCAN_BLOCKS ((N_NODES + 1023) / 1024)   // 49

// ---- scratch (device globals; no allocation allowed) ----
__device__ float g_xl  [N_NODES * HC];      // projected features (51.2MB, L2-resident)
__device__ float g_asrc[N_NODES * HEADS];
__device__ float g_adst[N_NODES * HEADS];
__device__ float g_den [N_NODES * HEADS];   // softmax denominators
__device__ int   g_deg [N_NODES];
__device__ int   g_incl[N_NODES];
__device__ int   g_bsum[SCAN_BLOCKS];
__device__ int   g_boff[SCAN_BLOCKS];
__device__ int   g_ptr [N_NODES + 1];       // CSR row ptr (by dst)
__device__ int   g_cur [N_NODES];
__device__ int   g_ssrc[TOT_E];             // dst-sorted: src node per slot
__device__ float g_sexp[TOT_E * HEADS];     // dst-sorted: exp(alpha) per slot (13.6MB)

__device__ __forceinline__ float lrelu(float a) { return a > 0.f ? a : NEG_SLOPE * a; }

__device__ __forceinline__ void red4(float* p, float a, float b, float c, float d) {
    asm volatile("red.global.add.v4.f32 [%0], {%1, %2, %3, %4};"
                 :: "l"(p), "f"(a), "f"(b), "f"(c), "f"(d) : "memory");
}
__device__ __forceinline__ void fma2(unsigned long long& acc,
                                     unsigned long long a, unsigned long long b) {
    asm("fma.rn.f32x2 %0, %1, %2, %0;" : "+l"(acc) : "l"(a), "l"(b));
}
__device__ __forceinline__ float f2lo(unsigned long long v) {
    return __uint_as_float((unsigned)(v & 0xFFFFFFFFull));
}
__device__ __forceinline__ float f2hi(unsigned long long v) {
    return __uint_as_float((unsigned)(v >> 32));
}

// ---------------- K0: zero deg + den ----------------
__global__ void k_init() {
    int i = blockIdx.x * blockDim.x + threadIdx.x;
    if (i < N_NODES) {
        g_deg[i] = 0;
        ((float4*)g_den)[i] = make_float4(0.f, 0.f, 0.f, 0.f);
    }
}

// ------- K1: xl = x @ W^T via fma.rn.f32x2, fused attention logits ------
__global__ void __launch_bounds__(256) k_gemm(const float* __restrict__ x,
                                              const float* __restrict__ W,
                                              const float* __restrict__ att_src,
                                              const float* __restrict__ att_dst) {
    __shared__ float xs[16 * IN_CH];          // 8KB
    __shared__ float red_s[8][16];
    __shared__ float red_d[8][16];
    const int n0 = blockIdx.x * 16;           // 50000 = 3125 * 16
    const int t  = threadIdx.x;               // output channel 0..255
    const int wid  = t >> 5;
    const int lane = t & 31;

    const float* xsrc = x + (size_t)n0 * IN_CH;
    #pragma unroll
    for (int i = t; i < 16 * IN_CH; i += 256) xs[i] = xsrc[i];
    __syncthreads();

    // packed accumulators: (even-k partial, odd-k partial)
    unsigned long long acc2[16];
    #pragma unroll
    for (int n = 0; n < 16; n++) acc2[n] = 0ull;

    const ulonglong2* Wr = (const ulonglong2*)(W + (size_t)t * IN_CH);
    #pragma unroll 4
    for (int kt = 0; kt < IN_CH / 4; kt++) {       // 4 k's per iter
        ulonglong2 w = Wr[kt];                     // pairs (k,k+1),(k+2,k+3)
        #pragma unroll
        for (int n = 0; n < 16; n++) {
            const unsigned long long* xp =
                (const unsigned long long*)&xs[n * IN_CH + kt * 4];
            fma2(acc2[n], w.x, xp[0]);
            fma2(acc2[n], w.y, xp[1]);
        }
    }

    float acc[16];
    #pragma unroll
    for (int n = 0; n < 16; n++) acc[n] = f2lo(acc2[n]) + f2hi(acc2[n]);

    #pragma unroll
    for (int n = 0; n < 16; n++)
        g_xl[(size_t)(n0 + n) * HC + t] = acc[n];

    // fused logits: reduce acc[n]*att over the 64 channels of head t>>6
    float as_t = att_src[t];                  // [H][C] flat == channel t
    float ad_t = att_dst[t];
    float ps[16], pd[16];
    #pragma unroll
    for (int n = 0; n < 16; n++) { ps[n] = acc[n] * as_t; pd[n] = acc[n] * ad_t; }
    #pragma unroll
    for (int off = 16; off; off >>= 1) {
        #pragma unroll
        for (int n = 0; n < 16; n++) {
            ps[n] += __shfl_xor_sync(0xFFFFFFFFu, ps[n], off);
            pd[n] += __shfl_xor_sync(0xFFFFFFFFu, pd[n], off);
        }
    }
    if (lane == 0) {
        #pragma unroll
        for (int n = 0; n < 16; n++) { red_s[wid][n] = ps[n]; red_d[wid][n] = pd[n]; }
    }
    __syncthreads();
    if (t < 64) {                             // head h spans warps 2h, 2h+1
        int h = t >> 4, n = t & 15;
        g_asrc[(size_t)(n0 + n) * 4 + h] = red_s[2 * h][n] + red_s[2 * h + 1][n];
    } else if (t < 128) {
        int u = t - 64, h = u >> 4, n = u & 15;
        g_adst[(size_t)(n0 + n) * 4 + h] = red_d[2 * h][n] + red_d[2 * h + 1][n];
    }
}

// ---------------- K2: dst-degree histogram ----------------
__global__ void k_hist(const int* __restrict__ ei) {
    int e = blockIdx.x * blockDim.x + threadIdx.x;
    if (e >= TOT_E) return;
    int d = (e < N_EDGES) ? ei[N_EDGES + e] : (e - N_EDGES);
    atomicAdd(&g_deg[d], 1);
}

// ---------------- K3a/b/c: prefix scan -> CSR ptr ----------------
__global__ void __launch_bounds__(1024) k_scanA() {
    __shared__ int s[1024];
    int i = blockIdx.x * 1024 + threadIdx.x;
    int v = (i < N_NODES) ? g_deg[i] : 0;
    s[threadIdx.x] = v;
    __syncthreads();
    #pragma unroll
    for (int off = 1; off < 1024; off <<= 1) {
        int u = (threadIdx.x >= off) ? s[threadIdx.x - off] : 0;
        __syncthreads();
        s[threadIdx.x] += u;
        __syncthreads();
    }
    if (i < N_NODES) g_incl[i] = s[threadIdx.x];
    if (threadIdx.x == 1023) g_bsum[blockIdx.x] = s[1023];
}
__global__ void k_scanB() {
    if (threadIdx.x == 0) {
        int run = 0;
        for (int b = 0; b < SCAN_BLOCKS; b++) { g_boff[b] = run; run += g_bsum[b]; }
    }
}
__global__ void __launch_bounds__(1024) k_scanC() {
    int i = blockIdx.x * 1024 + threadIdx.x;
    if (i >= N_NODES) return;
    int incl = g_incl[i] + g_boff[blockIdx.x];
    int excl = incl - g_deg[i];
    g_ptr[i] = excl;
    g_cur[i] = excl;
    if (i == N_NODES - 1) g_ptr[N_NODES] = incl;
}

// ------- K4: fused fill + exp + denominators (one edge pass) -------
__global__ void k_fill(const int* __restrict__ ei) {
    int e = blockIdx.x * blockDim.x + threadIdx.x;
    if (e >= TOT_E) return;
    int s, d;
    if (e < N_EDGES) { s = ei[e]; d = ei[N_EDGES + e]; }
    else             { s = d = e - N_EDGES; }
    int pos = atomicAdd(&g_cur[d], 1);
    float4 as = *(const float4*)&g_asrc[(size_t)s * 4];
    float4 ad = *(const float4*)&g_adst[(size_t)d * 4];
    float4 ex;
    ex.x = expf(lrelu(as.x + ad.x));
    ex.y = expf(lrelu(as.y + ad.y));
    ex.z = expf(lrelu(as.z + ad.z));
    ex.w = expf(lrelu(as.w + ad.w));
    g_ssrc[pos] = s;
    *(float4*)&g_sexp[(size_t)pos * 4] = ex;
    red4(&g_den[(size_t)d * 4], ex.x, ex.y, ex.z, ex.w);
}

// ------- K5: gather-aggregate, warp per node, fused bias+ELU -------
__global__ void __launch_bounds__(256) k_agg(const float* __restrict__ bias,
                                             float* __restrict__ out) {
    int w    = (blockIdx.x * blockDim.x + threadIdx.x) >> 5;   // node id
    int lane = threadIdx.x & 31;
    if (w >= N_NODES) return;
    const int d  = w;
    const int p0 = g_ptr[d];
    const int p1 = g_ptr[d + 1];

    float4 den = *(const float4*)&g_den[(size_t)d * 4];
    float4 idn = make_float4(1.f / den.x, 1.f / den.y, 1.f / den.z, 1.f / den.w);
    const bool lo = (lane < 16);   // lane -> float4 idx {lane, lane+32} -> heads {lane>>4, 2+(lane>>4)}

    float4 a0 = make_float4(0.f, 0.f, 0.f, 0.f);
    float4 a1 = make_float4(0.f, 0.f, 0.f, 0.f);

    int p = p0;
    for (; p + 2 <= p1; p += 2) {             // 2-way unroll: 4 gathers in flight
        int    sA  = g_ssrc[p];
        int    sB  = g_ssrc[p + 1];
        float4 exA = *(const float4*)&g_sexp[(size_t)p * 4];
        float4 exB = *(const float4*)&g_sexp[(size_t)(p + 1) * 4];
        const float4* xA = (const float4*)&g_xl[(size_t)sA * HC];
        const float4* xB = (const float4*)&g_xl[(size_t)sB * HC];
        float4 vA0 = xA[lane], vA1 = xA[lane + 32];
        float4 vB0 = xB[lane], vB1 = xB[lane + 32];
        float cA0 = lo ? exA.x * idn.x : exA.y * idn.y;
        float cA1 = lo ? exA.z * idn.z : exA.w * idn.w;
        float cB0 = lo ? exB.x * idn.x : exB.y * idn.y;
        float cB1 = lo ? exB.z * idn.z : exB.w * idn.w;
        a0.x += cA0 * vA0.x; a0.y += cA0 * vA0.y; a0.z += cA0 * vA0.z; a0.w += cA0 * vA0.w;
        a1.x += cA1 * vA1.x; a1.y += cA1 * vA1.y; a1.z += cA1 * vA1.z; a1.w += cA1 * vA1.w;
        a0.x += cB0 * vB0.x; a0.y += cB0 * vB0.y; a0.z += cB0 * vB0.z; a0.w += cB0 * vB0.w;
        a1.x += cB1 * vB1.x; a1.y += cB1 * vB1.y; a1.z += cB1 * vB1.z; a1.w += cB1 * vB1.w;
    }
    if (p < p1) {
        int    s  = g_ssrc[p];
        float4 ex = *(const float4*)&g_sexp[(size_t)p * 4];
        const float4* xp = (const float4*)&g_xl[(size_t)s * HC];
        float4 v0 = xp[lane], v1 = xp[lane + 32];
        float c0 = lo ? ex.x * idn.x : ex.y * idn.y;
        float c1 = lo ? ex.z * idn.z : ex.w * idn.w;
        a0.x += c0 * v0.x; a0.y += c0 * v0.y; a0.z += c0 * v0.z; a0.w += c0 * v0.w;
        a1.x += c1 * v1.x; a1.y += c1 * v1.y; a1.z += c1 * v1.z; a1.w += c1 * v1.w;
    }

    float4 b0 = ((const float4*)bias)[lane];
    float4 b1 = ((const float4*)bias)[lane + 32];
    a0.x += b0.x; a0.y += b0.y; a0.z += b0.z; a0.w += b0.w;
    a1.x += b1.x; a1.y += b1.y; a1.z += b1.z; a1.w += b1.w;
    a0.x = a0.x > 0.f ? a0.x : expm1f(a0.x);
    a0.y = a0.y > 0.f ? a0.y : expm1f(a0.y);
    a0.z = a0.z > 0.f ? a0.z : expm1f(a0.z);
    a0.w = a0.w > 0.f ? a0.w : expm1f(a0.w);
    a1.x = a1.x > 0.f ? a1.x : expm1f(a1.x);
    a1.y = a1.y > 0.f ? a1.y : expm1f(a1.y);
    a1.z = a1.z > 0.f ? a1.z : expm1f(a1.z);
    a1.w = a1.w > 0.f ? a1.w : expm1f(a1.w);

    float4* op = (float4*)(out + (size_t)d * HC);
    op[lane]      = a0;
    op[lane + 32] = a1;
}

extern "C" void kernel_launch(void* const* d_in, const int* in_sizes, int n_in,
                              void* d_out, int out_size) {
    const float* x    = (const float*)d_in[0];
    const int*   ei   = (const int*)d_in[1];    // int32 (JAX x64 disabled)
    const float* W    = (const float*)d_in[2];
    const float* asrc = (const float*)d_in[3];
    const float* adst = (const float*)d_in[4];
    const float* bias = (const float*)d_in[5];
    float* out = (float*)d_out;

    (void)in_sizes; (void)n_in; (void)out_size;

    k_init<<<(N_NODES + 255) / 256, 256>>>();
    k_gemm<<<N_NODES / 16, 256>>>(x, W, asrc, adst);
    k_hist<<<(TOT_E + 255) / 256, 256>>>(ei);
    k_scanA<<<SCAN_BLOCKS, 1024>>>();
    k_scanB<<<1, 32>>>();
    k_scanC<<<SCAN_BLOCKS, 1024>>>();
    k_fill<<<(TOT_E + 255) / 256, 256>>>(ei);
    k_agg<<<(N_NODES * 32 + 255) / 256, 256>>>(bias, out);
}